// round 15
// baseline (speedup 1.0000x reference)
#include <cuda_runtime.h>
#include <cstdint>

#define NLEV   12
#define HSIZE  524288
#define HMASK  (HSIZE - 1)

// fragment-layout float offsets inside g_dup
// W frag float4 per (tile,lane): (b0_hi, b1_hi, b0_lo, b1_lo)
#define W1F 0       // 12 tiles * 32 lanes * 4 = 1536
#define W2F 1536    // 8 * 128 = 1024
#define W3F 2560    // 2 * 128 = 256
#define W4F 2816    // 1 * 128 = 128
#define B1O 2944    // 32
#define B2O 2976    // 16
#define B3O 2992    // 8
#define B4O 3000    // 8 (b4, then zeros)
#define GTOT 3072

__device__ __align__(16) float g_dup[GTOT];

__device__ __forceinline__ uint32_t tf32_rna(float v) {
    uint32_t r; asm("cvt.rna.tf32.f32 %0, %1;" : "=r"(r) : "f"(v)); return r;
}

// D = A*B + D, m16n8k8 tf32 (A row-major frag, B col-major frag, fp32 acc)
__device__ __forceinline__ void mma8(float* c, const uint32_t* a, uint32_t b0, uint32_t b1) {
    asm("mma.sync.aligned.m16n8k8.row.col.f32.tf32.tf32.f32 "
        "{%0,%1,%2,%3}, {%4,%5,%6,%7}, {%8,%9}, {%0,%1,%2,%3};"
        : "+f"(c[0]), "+f"(c[1]), "+f"(c[2]), "+f"(c[3])
        : "r"(a[0]), "r"(a[1]), "r"(a[2]), "r"(a[3]), "r"(b0), "r"(b1));
}

__device__ __forceinline__ void lrelu4(float* c) {
    #pragma unroll
    for (int i = 0; i < 4; i++) c[i] = fmaxf(c[i], 0.01f * c[i]);
}

// split fp32 -> (tf32 hi, tf32 lo)
__device__ __forceinline__ void split1(float v, uint32_t& hi, uint32_t& lo) {
    hi = tf32_rna(v);
    lo = tf32_rna(v - __uint_as_float(hi));
}

// convert D fragment [16x8] (c0..c3) to A fragment (row-major) via shuffles.
// D: c0=(g,2u) c1=(g,2u+1) c2=(g+8,2u) c3=(g+8,2u+1)
// A: a0=(g,u)  a1=(g+8,u)  a2=(g,u+4)  a3=(g+8,u+4)
__device__ __forceinline__ void d2a(const float* d, float* a, int lane) {
    int u = lane & 3;
    int srcA = (lane & 28) + (u >> 1);
    int srcB = srcA + 2;
    float v0 = __shfl_sync(0xffffffffu, d[0], srcA);
    float v1 = __shfl_sync(0xffffffffu, d[1], srcA);
    float v2 = __shfl_sync(0xffffffffu, d[2], srcA);
    float v3 = __shfl_sync(0xffffffffu, d[3], srcA);
    float w0 = __shfl_sync(0xffffffffu, d[0], srcB);
    float w1 = __shfl_sync(0xffffffffu, d[1], srcB);
    float w2 = __shfl_sync(0xffffffffu, d[2], srcB);
    float w3 = __shfl_sync(0xffffffffu, d[3], srcB);
    bool odd = (u & 1);
    a[0] = odd ? v1 : v0;
    a[1] = odd ? v3 : v2;
    a[2] = odd ? w1 : w0;
    a[3] = odd ? w3 : w2;
}

__device__ __forceinline__ void splitA(const float* af, uint32_t* ah, uint32_t* al) {
    #pragma unroll
    for (int i = 0; i < 4; i++) split1(af[i], ah[i], al[i]);
}

__device__ __forceinline__ float gatherf(const float* __restrict__ tables,
                                         int lev, int comp, float qx, float qy, float s) {
    int d0 = __float2int_rd(qx * s);
    int d1 = __float2int_rd(qy * s);
    unsigned h = ((unsigned)d0 * 73856093u + (unsigned)d1 * 19349663u) & HMASK;
    return tables[(((size_t)lev << 19) + h) * 2 + comp];
}

// ---------------- prep: pack weights into per-lane MMA B-fragments ----------------
__global__ void prep_kernel(const float* __restrict__ W1, const float* __restrict__ b1,
                            const float* __restrict__ W2, const float* __restrict__ b2,
                            const float* __restrict__ W3, const float* __restrict__ b3,
                            const float* __restrict__ W4, const float* __restrict__ b4)
{
    int t = threadIdx.x;
    if (t < 736) {
        int lane = t & 31;
        const float* Wsrc; int Kdim, kt, nt, foff; bool isW4 = false;
        if (t < 384)      { int f = t >> 5;          kt = f / 4; nt = f % 4; Wsrc = W1; Kdim = 24; foff = W1F + (f * 32 + lane) * 4; }
        else if (t < 640) { int f = (t - 384) >> 5;  kt = f / 2; nt = f % 2; Wsrc = W2; Kdim = 32; foff = W2F + (f * 32 + lane) * 4; }
        else if (t < 704) { int f = (t - 640) >> 5;  kt = f;     nt = 0;     Wsrc = W3; Kdim = 16; foff = W3F + (f * 32 + lane) * 4; }
        else              { kt = 0; nt = 0; Wsrc = W4; Kdim = 8; foff = W4F + lane * 4; isW4 = true; }
        int k = kt * 8 + (lane & 3);
        int n = nt * 8 + (lane >> 2);
        bool valid = !isW4 || (n == 0);
        float v0 = valid ? Wsrc[n * Kdim + k]     : 0.0f;
        float v1 = valid ? Wsrc[n * Kdim + k + 4] : 0.0f;
        uint32_t h0, l0, h1, l1;
        split1(v0, h0, l0);
        split1(v1, h1, l1);
        g_dup[foff + 0] = __uint_as_float(h0);
        g_dup[foff + 1] = __uint_as_float(h1);
        g_dup[foff + 2] = __uint_as_float(l0);
        g_dup[foff + 3] = __uint_as_float(l1);
    } else if (t < 768) {
        g_dup[B1O + t - 736] = b1[t - 736];
    } else if (t < 784) {
        g_dup[B2O + t - 768] = b2[t - 768];
    } else if (t < 792) {
        g_dup[B3O + t - 784] = b3[t - 784];
    } else if (t < 800) {
        g_dup[B4O + t - 792] = (t == 792) ? b4[0] : 0.0f;
    }
}

// ---------------- main: warp = 16-point tile, tf32 split MMA MLP ----------------
__global__ __launch_bounds__(128, 4)
void nhgrid_mma(const float* __restrict__ x,
                const float* __restrict__ tables,
                float* __restrict__ out, int n_points, int ntiles)
{
    int lane = threadIdx.x & 31;
    int warpg = blockIdx.x * (blockDim.x >> 5) + (threadIdx.x >> 5);
    int nwarps = gridDim.x * (blockDim.x >> 5);
    int u = lane & 3, g = lane >> 2;
    int comp = u & 1;
    bool hb = (u >= 2);
    // per-lane spacings: levels 4kt+(u>>1) and +2; (full list = Python 256.0//1.6**(11-i))
    float sp[3][2];
    sp[0][0] = hb ? 2.0f  : 1.0f;   sp[0][1] = hb ? 5.0f   : 3.0f;
    sp[1][0] = hb ? 15.0f : 9.0f;   sp[1][1] = hb ? 39.0f  : 24.0f;
    sp[2][0] = hb ? 99.0f : 62.0f;  sp[2][1] = hb ? 256.0f : 159.0f;

    for (int tile = warpg; tile < ntiles; tile += nwarps) {
        int pbase = tile * 16;
        int p0 = pbase + g, p1 = p0 + 8;
        int m0 = min(p0, n_points - 1), m1 = min(p1, n_points - 1);
        float2 X0 = *reinterpret_cast<const float2*>(x + 2 * m0);
        float2 X1 = *reinterpret_cast<const float2*>(x + 2 * m1);
        float q00 = fmaf(X0.x, 0.5f, 0.5f), q01 = fmaf(X0.y, 0.5f, 0.5f);
        float q10 = fmaf(X1.x, 0.5f, 0.5f), q11 = fmaf(X1.y, 0.5f, 0.5f);

        // gather features straight into A fragments (3 k-tiles of [16x8])
        uint32_t Ah[3][4], Al[3][4];
        #pragma unroll
        for (int kt = 0; kt < 3; kt++) {
            int lev0 = 4 * kt + (u >> 1);
            int lev1 = lev0 + 2;
            float s0 = sp[kt][0], s1 = sp[kt][1];
            float af[4];
            af[0] = gatherf(tables, lev0, comp, q00, q01, s0);  // (g, col)
            af[1] = gatherf(tables, lev0, comp, q10, q11, s0);  // (g+8, col)
            af[2] = gatherf(tables, lev1, comp, q00, q01, s1);  // (g, col+4)
            af[3] = gatherf(tables, lev1, comp, q10, q11, s1);  // (g+8, col+4)
            splitA(af, Ah[kt], Al[kt]);
        }

        // ---- layer 1: [16x24] @ [24x32] -> 4 n-tiles ----
        float d1t[4][4];
        #pragma unroll
        for (int nt = 0; nt < 4; nt++) {
            float2 bb = *reinterpret_cast<const float2*>(g_dup + B1O + nt * 8 + 2 * u);
            float* c = d1t[nt];
            c[0] = bb.x; c[1] = bb.y; c[2] = bb.x; c[3] = bb.y;
            #pragma unroll
            for (int kt = 0; kt < 3; kt++) {
                float4 wq = *reinterpret_cast<const float4*>(g_dup + W1F + ((kt * 4 + nt) * 32 + lane) * 4);
                uint32_t bh0 = __float_as_uint(wq.x), bh1 = __float_as_uint(wq.y);
                uint32_t bl0 = __float_as_uint(wq.z), bl1 = __float_as_uint(wq.w);
                mma8(c, Ah[kt], bh0, bh1);
                mma8(c, Al[kt], bh0, bh1);
                mma8(c, Ah[kt], bl0, bl1);
            }
            lrelu4(c);
        }

        // ---- layer 2: [16x32] @ [32x16] -> 2 n-tiles ----
        uint32_t A2h[4][4], A2l[4][4];
        #pragma unroll
        for (int kt = 0; kt < 4; kt++) {
            float af[4];
            d2a(d1t[kt], af, lane);
            splitA(af, A2h[kt], A2l[kt]);
        }
        float d2t[2][4];
        #pragma unroll
        for (int nt = 0; nt < 2; nt++) {
            float2 bb = *reinterpret_cast<const float2*>(g_dup + B2O + nt * 8 + 2 * u);
            float* c = d2t[nt];
            c[0] = bb.x; c[1] = bb.y; c[2] = bb.x; c[3] = bb.y;
            #pragma unroll
            for (int kt = 0; kt < 4; kt++) {
                float4 wq = *reinterpret_cast<const float4*>(g_dup + W2F + ((kt * 2 + nt) * 32 + lane) * 4);
                uint32_t bh0 = __float_as_uint(wq.x), bh1 = __float_as_uint(wq.y);
                uint32_t bl0 = __float_as_uint(wq.z), bl1 = __float_as_uint(wq.w);
                mma8(c, A2h[kt], bh0, bh1);
                mma8(c, A2l[kt], bh0, bh1);
                mma8(c, A2h[kt], bl0, bl1);
            }
            lrelu4(c);
        }

        // ---- layer 3: [16x16] @ [16x8] -> 1 n-tile ----
        uint32_t A3h[2][4], A3l[2][4];
        #pragma unroll
        for (int kt = 0; kt < 2; kt++) {
            float af[4];
            d2a(d2t[kt], af, lane);
            splitA(af, A3h[kt], A3l[kt]);
        }
        float d3t[4];
        {
            float2 bb = *reinterpret_cast<const float2*>(g_dup + B3O + 2 * u);
            d3t[0] = bb.x; d3t[1] = bb.y; d3t[2] = bb.x; d3t[3] = bb.y;
            #pragma unroll
            for (int kt = 0; kt < 2; kt++) {
                float4 wq = *reinterpret_cast<const float4*>(g_dup + W3F + (kt * 32 + lane) * 4);
                uint32_t bh0 = __float_as_uint(wq.x), bh1 = __float_as_uint(wq.y);
                uint32_t bl0 = __float_as_uint(wq.z), bl1 = __float_as_uint(wq.w);
                mma8(d3t, A3h[kt], bh0, bh1);
                mma8(d3t, A3l[kt], bh0, bh1);
                mma8(d3t, A3h[kt], bl0, bl1);
            }
            lrelu4(d3t);
        }

        // ---- layer 4: [16x8] @ [8x8 (1 col)] ----
        uint32_t A4h[4], A4l[4];
        {
            float af[4];
            d2a(d3t, af, lane);
            splitA(af, A4h, A4l);
        }
        float d4[4];
        {
            float2 bb = *reinterpret_cast<const float2*>(g_dup + B4O + 2 * u);
            d4[0] = bb.x; d4[1] = bb.y; d4[2] = bb.x; d4[3] = bb.y;
            float4 wq = *reinterpret_cast<const float4*>(g_dup + W4F + lane * 4);
            uint32_t bh0 = __float_as_uint(wq.x), bh1 = __float_as_uint(wq.y);
            uint32_t bl0 = __float_as_uint(wq.z), bl1 = __float_as_uint(wq.w);
            mma8(d4, A4h, bh0, bh1);
            mma8(d4, A4l, bh0, bh1);
            mma8(d4, A4h, bl0, bl1);
            lrelu4(d4);   // forward's final lrelu
            lrelu4(d4);   // extra lrelu (trueRange=False)
        }

        // col 0 lives on lanes with u==0: c0 = row g, c2 = row g+8
        if (u == 0) {
            if (p0 < n_points) out[p0] = d4[0];
            if (p1 < n_points) out[p1] = d4[2];
        }
    }
}

extern "C" void kernel_launch(void* const* d_in, const int* in_sizes, int n_in,
                              void* d_out, int out_size)
{
    const float* x      = (const float*)d_in[0];
    const float* tables = (const float*)d_in[1];
    const float* W1     = (const float*)d_in[2];
    const float* b1     = (const float*)d_in[3];
    const float* W2     = (const float*)d_in[4];
    const float* b2     = (const float*)d_in[5];
    const float* W3     = (const float*)d_in[6];
    const float* b3     = (const float*)d_in[7];
    const float* W4     = (const float*)d_in[8];
    const float* b4     = (const float*)d_in[9];
    float* out = (float*)d_out;

    int n_points = in_sizes[0] / 2;
    int ntiles = (n_points + 15) / 16;

    prep_kernel<<<1, 1024>>>(W1, b1, W2, b2, W3, b3, W4, b4);

    int threads = 128;
    int blocks = 3907;           // 15628 warps; ~8 tiles per warp at 2M points
    nhgrid_mma<<<blocks, threads>>>(x, tables, out, n_points, ntiles);
}

// round 16
// speedup vs baseline: 1.1113x; 1.1113x over previous
#include <cuda_runtime.h>
#include <cstdint>

#define NLEV   12
#define HSIZE  524288
#define HMASK  (HSIZE - 1)

// fragment-layout float offsets inside g_dup
// W frag float4 per (tile,lane): (b0_hi, b1_hi, b0_lo, b1_lo)
#define W1F 0       // 12 tiles * 32 lanes * 4 = 1536
#define W2F 1536    // 8 * 128 = 1024
#define W3F 2560    // 2 * 128 = 256
#define W4F 2816    // 1 * 128 = 128
#define B1O 2944    // 32
#define B2O 2976    // 16
#define B3O 2992    // 8
#define B4O 3000    // 8 (b4, then zeros)
#define GTOT 3072

__device__ __align__(16) float g_dup[GTOT];

__device__ __forceinline__ uint32_t tf32_rna(float v) {
    uint32_t r; asm("cvt.rna.tf32.f32 %0, %1;" : "=r"(r) : "f"(v)); return r;
}

// D = A*B + D, m16n8k8 tf32 (A row-major frag, B col-major frag, fp32 acc)
__device__ __forceinline__ void mma8(float* c, const uint32_t* a, uint32_t b0, uint32_t b1) {
    asm("mma.sync.aligned.m16n8k8.row.col.f32.tf32.tf32.f32 "
        "{%0,%1,%2,%3}, {%4,%5,%6,%7}, {%8,%9}, {%0,%1,%2,%3};"
        : "+f"(c[0]), "+f"(c[1]), "+f"(c[2]), "+f"(c[3])
        : "r"(a[0]), "r"(a[1]), "r"(a[2]), "r"(a[3]), "r"(b0), "r"(b1));
}

__device__ __forceinline__ void lrelu4(float* c) {
    #pragma unroll
    for (int i = 0; i < 4; i++) c[i] = fmaxf(c[i], 0.01f * c[i]);
}

// split fp32 -> (tf32 hi, tf32 lo)
__device__ __forceinline__ void split1(float v, uint32_t& hi, uint32_t& lo) {
    hi = tf32_rna(v);
    lo = tf32_rna(v - __uint_as_float(hi));
}

// convert D fragment [16x8] (c0..c3) to A fragment (row-major) via shuffles.
__device__ __forceinline__ void d2a(const float* d, float* a, int lane) {
    int u = lane & 3;
    int srcA = (lane & 28) + (u >> 1);
    int srcB = srcA + 2;
    float v0 = __shfl_sync(0xffffffffu, d[0], srcA);
    float v1 = __shfl_sync(0xffffffffu, d[1], srcA);
    float v2 = __shfl_sync(0xffffffffu, d[2], srcA);
    float v3 = __shfl_sync(0xffffffffu, d[3], srcA);
    float w0 = __shfl_sync(0xffffffffu, d[0], srcB);
    float w1 = __shfl_sync(0xffffffffu, d[1], srcB);
    float w2 = __shfl_sync(0xffffffffu, d[2], srcB);
    float w3 = __shfl_sync(0xffffffffu, d[3], srcB);
    bool odd = (u & 1);
    a[0] = odd ? v1 : v0;
    a[1] = odd ? v3 : v2;
    a[2] = odd ? w1 : w0;
    a[3] = odd ? w3 : w2;
}

__device__ __forceinline__ void splitA(const float* af, uint32_t* ah, uint32_t* al) {
    #pragma unroll
    for (int i = 0; i < 4; i++) split1(af[i], ah[i], al[i]);
}

// hi-only conversion (layers 2-4: activations truncated to tf32, no lo term)
__device__ __forceinline__ void cvtA(const float* af, uint32_t* ah) {
    #pragma unroll
    for (int i = 0; i < 4; i++) ah[i] = tf32_rna(af[i]);
}

__device__ __forceinline__ float gatherf(const float* __restrict__ tables,
                                         int lev, int comp, float qx, float qy, float s) {
    int d0 = __float2int_rd(qx * s);
    int d1 = __float2int_rd(qy * s);
    unsigned h = ((unsigned)d0 * 73856093u + (unsigned)d1 * 19349663u) & HMASK;
    return tables[(((size_t)lev << 19) + h) * 2 + comp];
}

// ---------------- prep: pack weights into per-lane MMA B-fragments ----------------
__global__ void prep_kernel(const float* __restrict__ W1, const float* __restrict__ b1,
                            const float* __restrict__ W2, const float* __restrict__ b2,
                            const float* __restrict__ W3, const float* __restrict__ b3,
                            const float* __restrict__ W4, const float* __restrict__ b4)
{
    int t = threadIdx.x;
    if (t < 736) {
        int lane = t & 31;
        const float* Wsrc; int Kdim, kt, nt, foff; bool isW4 = false;
        if (t < 384)      { int f = t >> 5;          kt = f / 4; nt = f % 4; Wsrc = W1; Kdim = 24; foff = W1F + (f * 32 + lane) * 4; }
        else if (t < 640) { int f = (t - 384) >> 5;  kt = f / 2; nt = f % 2; Wsrc = W2; Kdim = 32; foff = W2F + (f * 32 + lane) * 4; }
        else if (t < 704) { int f = (t - 640) >> 5;  kt = f;     nt = 0;     Wsrc = W3; Kdim = 16; foff = W3F + (f * 32 + lane) * 4; }
        else              { kt = 0; nt = 0; Wsrc = W4; Kdim = 8; foff = W4F + lane * 4; isW4 = true; }
        int k = kt * 8 + (lane & 3);
        int n = nt * 8 + (lane >> 2);
        bool valid = !isW4 || (n == 0);
        float v0 = valid ? Wsrc[n * Kdim + k]     : 0.0f;
        float v1 = valid ? Wsrc[n * Kdim + k + 4] : 0.0f;
        uint32_t h0, l0, h1, l1;
        split1(v0, h0, l0);
        split1(v1, h1, l1);
        g_dup[foff + 0] = __uint_as_float(h0);
        g_dup[foff + 1] = __uint_as_float(h1);
        g_dup[foff + 2] = __uint_as_float(l0);
        g_dup[foff + 3] = __uint_as_float(l1);
    } else if (t < 768) {
        g_dup[B1O + t - 736] = b1[t - 736];
    } else if (t < 784) {
        g_dup[B2O + t - 768] = b2[t - 768];
    } else if (t < 792) {
        g_dup[B3O + t - 784] = b3[t - 784];
    } else if (t < 800) {
        g_dup[B4O + t - 792] = (t == 792) ? b4[0] : 0.0f;
    }
}

// ---------------- main: warp = 16-point tile, weights hoisted to registers ----------------
__global__ __launch_bounds__(128, 3)
void nhgrid_mma(const float* __restrict__ x,
                const float* __restrict__ tables,
                float* __restrict__ out, int n_points, int ntiles)
{
    int lane = threadIdx.x & 31;
    int warpg = blockIdx.x * (blockDim.x >> 5) + (threadIdx.x >> 5);
    int nwarps = gridDim.x * (blockDim.x >> 5);
    int u = lane & 3, g = lane >> 2;
    int comp = u & 1;
    bool hb = (u >= 2);
    // per-lane spacings (full list = Python 256.0//1.6**(11-i))
    float sp[3][2];
    sp[0][0] = hb ? 2.0f  : 1.0f;   sp[0][1] = hb ? 5.0f   : 3.0f;
    sp[1][0] = hb ? 15.0f : 9.0f;   sp[1][1] = hb ? 39.0f  : 24.0f;
    sp[2][0] = hb ? 99.0f : 62.0f;  sp[2][1] = hb ? 256.0f : 159.0f;

    // ---- hoist loop-invariant weights/biases into registers ----
    float4 W1r[12];
    #pragma unroll
    for (int f = 0; f < 12; f++)
        W1r[f] = *reinterpret_cast<const float4*>(g_dup + W1F + (f * 32 + lane) * 4);
    float4 W3r[2];
    #pragma unroll
    for (int f = 0; f < 2; f++)
        W3r[f] = *reinterpret_cast<const float4*>(g_dup + W3F + (f * 32 + lane) * 4);
    float4 W4r = *reinterpret_cast<const float4*>(g_dup + W4F + lane * 4);
    float2 B1r[4];
    #pragma unroll
    for (int nt = 0; nt < 4; nt++)
        B1r[nt] = *reinterpret_cast<const float2*>(g_dup + B1O + nt * 8 + 2 * u);
    float2 B2r[2];
    #pragma unroll
    for (int nt = 0; nt < 2; nt++)
        B2r[nt] = *reinterpret_cast<const float2*>(g_dup + B2O + nt * 8 + 2 * u);
    float2 B3r = *reinterpret_cast<const float2*>(g_dup + B3O + 2 * u);
    float2 B4r = *reinterpret_cast<const float2*>(g_dup + B4O + 2 * u);

    for (int tile = warpg; tile < ntiles; tile += nwarps) {
        int pbase = tile * 16;
        int p0 = pbase + g, p1 = p0 + 8;
        int m0 = min(p0, n_points - 1), m1 = min(p1, n_points - 1);
        float2 X0 = *reinterpret_cast<const float2*>(x + 2 * m0);
        float2 X1 = *reinterpret_cast<const float2*>(x + 2 * m1);
        float q00 = fmaf(X0.x, 0.5f, 0.5f), q01 = fmaf(X0.y, 0.5f, 0.5f);
        float q10 = fmaf(X1.x, 0.5f, 0.5f), q11 = fmaf(X1.y, 0.5f, 0.5f);

        // gather features straight into A fragments (3 k-tiles of [16x8])
        uint32_t Ah[3][4], Al[3][4];
        #pragma unroll
        for (int kt = 0; kt < 3; kt++) {
            int lev0 = 4 * kt + (u >> 1);
            int lev1 = lev0 + 2;
            float s0 = sp[kt][0], s1 = sp[kt][1];
            float af[4];
            af[0] = gatherf(tables, lev0, comp, q00, q01, s0);
            af[1] = gatherf(tables, lev0, comp, q10, q11, s0);
            af[2] = gatherf(tables, lev1, comp, q00, q01, s1);
            af[3] = gatherf(tables, lev1, comp, q10, q11, s1);
            splitA(af, Ah[kt], Al[kt]);
        }

        // ---- layer 1: [16x24] @ [24x32], full 3-MMA split, weights from regs ----
        float d1t[4][4];
        #pragma unroll
        for (int nt = 0; nt < 4; nt++) {
            float* c = d1t[nt];
            c[0] = B1r[nt].x; c[1] = B1r[nt].y; c[2] = B1r[nt].x; c[3] = B1r[nt].y;
            #pragma unroll
            for (int kt = 0; kt < 3; kt++) {
                float4 wq = W1r[kt * 4 + nt];
                uint32_t bh0 = __float_as_uint(wq.x), bh1 = __float_as_uint(wq.y);
                uint32_t bl0 = __float_as_uint(wq.z), bl1 = __float_as_uint(wq.w);
                mma8(c, Ah[kt], bh0, bh1);
                mma8(c, Al[kt], bh0, bh1);
                mma8(c, Ah[kt], bl0, bl1);
            }
            lrelu4(c);
        }

        // prefetch W2 fragments now; loads complete under the shuffle phase
        float4 W2r[8];
        #pragma unroll
        for (int f = 0; f < 8; f++)
            W2r[f] = *reinterpret_cast<const float4*>(g_dup + W2F + (f * 32 + lane) * 4);

        // ---- layer 2: [16x32] @ [32x16], A hi-only (2 MMAs per frag) ----
        uint32_t A2h[4][4];
        #pragma unroll
        for (int kt = 0; kt < 4; kt++) {
            float af[4];
            d2a(d1t[kt], af, lane);
            cvtA(af, A2h[kt]);
        }
        float d2t[2][4];
        #pragma unroll
        for (int nt = 0; nt < 2; nt++) {
            float* c = d2t[nt];
            c[0] = B2r[nt].x; c[1] = B2r[nt].y; c[2] = B2r[nt].x; c[3] = B2r[nt].y;
            #pragma unroll
            for (int kt = 0; kt < 4; kt++) {
                float4 wq = W2r[kt * 2 + nt];
                uint32_t bh0 = __float_as_uint(wq.x), bh1 = __float_as_uint(wq.y);
                uint32_t bl0 = __float_as_uint(wq.z), bl1 = __float_as_uint(wq.w);
                mma8(c, A2h[kt], bh0, bh1);
                mma8(c, A2h[kt], bl0, bl1);
            }
            lrelu4(c);
        }

        // ---- layer 3: [16x16] @ [16x8], A hi-only ----
        uint32_t A3h[2][4];
        #pragma unroll
        for (int kt = 0; kt < 2; kt++) {
            float af[4];
            d2a(d2t[kt], af, lane);
            cvtA(af, A3h[kt]);
        }
        float d3t[4];
        {
            d3t[0] = B3r.x; d3t[1] = B3r.y; d3t[2] = B3r.x; d3t[3] = B3r.y;
            #pragma unroll
            for (int kt = 0; kt < 2; kt++) {
                float4 wq = W3r[kt];
                uint32_t bh0 = __float_as_uint(wq.x), bh1 = __float_as_uint(wq.y);
                uint32_t bl0 = __float_as_uint(wq.z), bl1 = __float_as_uint(wq.w);
                mma8(d3t, A3h[kt], bh0, bh1);
                mma8(d3t, A3h[kt], bl0, bl1);
            }
            lrelu4(d3t);
        }

        // ---- layer 4: [16x8] @ [8x8 (1 col)], A hi-only ----
        uint32_t A4h[4];
        {
            float af[4];
            d2a(d3t, af, lane);
            cvtA(af, A4h);
        }
        float d4[4];
        {
            d4[0] = B4r.x; d4[1] = B4r.y; d4[2] = B4r.x; d4[3] = B4r.y;
            uint32_t bh0 = __float_as_uint(W4r.x), bh1 = __float_as_uint(W4r.y);
            uint32_t bl0 = __float_as_uint(W4r.z), bl1 = __float_as_uint(W4r.w);
            mma8(d4, A4h, bh0, bh1);
            mma8(d4, A4h, bl0, bl1);
            lrelu4(d4);   // forward's final lrelu
            lrelu4(d4);   // extra lrelu (trueRange=False)
        }

        // col 0 lives on lanes with u==0: c0 = row g, c2 = row g+8
        if (u == 0) {
            if (p0 < n_points) out[p0] = d4[0];
            if (p1 < n_points) out[p1] = d4[2];
        }
    }
}

extern "C" void kernel_launch(void* const* d_in, const int* in_sizes, int n_in,
                              void* d_out, int out_size)
{
    const float* x      = (const float*)d_in[0];
    const float* tables = (const float*)d_in[1];
    const float* W1     = (const float*)d_in[2];
    const float* b1     = (const float*)d_in[3];
    const float* W2     = (const float*)d_in[4];
    const float* b2     = (const float*)d_in[5];
    const float* W3     = (const float*)d_in[6];
    const float* b3     = (const float*)d_in[7];
    const float* W4     = (const float*)d_in[8];
    const float* b4     = (const float*)d_in[9];
    float* out = (float*)d_out;

    int n_points = in_sizes[0] / 2;
    int ntiles = (n_points + 15) / 16;

    prep_kernel<<<1, 1024>>>(W1, b1, W2, b2, W3, b3, W4, b4);

    int threads = 128;
    int blocks = 3907;           // 15628 warps; ~8 tiles per warp at 2M points
    nhgrid_mma<<<blocks, threads>>>(x, tables, out, n_points, ntiles);
}

// round 17
// speedup vs baseline: 1.2267x; 1.1038x over previous
#include <cuda_runtime.h>
#include <cstdint>

#define NLEV   12
#define HSIZE  524288
#define HMASK  (HSIZE - 1)

// fragment-layout float offsets inside g_dup / sWf
// W frag float4 per (tile,lane): (b0_hi, b1_hi, b0_lo, b1_lo)
#define W1F 0       // 12 tiles * 32 lanes * 4 = 1536
#define W2F 1536    // 8 * 128 = 1024
#define W3F 2560    // 2 * 128 = 256
#define W4F 2816    // 1 * 128 = 128
#define B1O 2944    // 32
#define B2O 2976    // 16
#define B3O 2992    // 8
#define B4O 3000    // 8 (b4, then zeros)
#define GTOT 3072

__device__ __align__(16) float g_dup[GTOT];

__device__ __forceinline__ uint32_t tf32_rna(float v) {
    uint32_t r; asm("cvt.rna.tf32.f32 %0, %1;" : "=r"(r) : "f"(v)); return r;
}

// D = A*B + D, m16n8k8 tf32 (A row-major frag, B col-major frag, fp32 acc)
__device__ __forceinline__ void mma8(float* c, const uint32_t* a, uint32_t b0, uint32_t b1) {
    asm("mma.sync.aligned.m16n8k8.row.col.f32.tf32.tf32.f32 "
        "{%0,%1,%2,%3}, {%4,%5,%6,%7}, {%8,%9}, {%0,%1,%2,%3};"
        : "+f"(c[0]), "+f"(c[1]), "+f"(c[2]), "+f"(c[3])
        : "r"(a[0]), "r"(a[1]), "r"(a[2]), "r"(a[3]), "r"(b0), "r"(b1));
}

__device__ __forceinline__ void lrelu4(float* c) {
    #pragma unroll
    for (int i = 0; i < 4; i++) c[i] = fmaxf(c[i], 0.01f * c[i]);
}

// split fp32 -> (tf32 hi, tf32 lo) -- used by prep only
__device__ __forceinline__ void split1(float v, uint32_t& hi, uint32_t& lo) {
    hi = tf32_rna(v);
    lo = tf32_rna(v - __uint_as_float(hi));
}

// convert D fragment [16x8] (c0..c3) to A fragment (row-major) via shuffles.
__device__ __forceinline__ void d2a(const float* d, float* a, int lane) {
    int u = lane & 3;
    int srcA = (lane & 28) + (u >> 1);
    int srcB = srcA + 2;
    float v0 = __shfl_sync(0xffffffffu, d[0], srcA);
    float v1 = __shfl_sync(0xffffffffu, d[1], srcA);
    float v2 = __shfl_sync(0xffffffffu, d[2], srcA);
    float v3 = __shfl_sync(0xffffffffu, d[3], srcA);
    float w0 = __shfl_sync(0xffffffffu, d[0], srcB);
    float w1 = __shfl_sync(0xffffffffu, d[1], srcB);
    float w2 = __shfl_sync(0xffffffffu, d[2], srcB);
    float w3 = __shfl_sync(0xffffffffu, d[3], srcB);
    bool odd = (u & 1);
    a[0] = odd ? v1 : v0;
    a[1] = odd ? v3 : v2;
    a[2] = odd ? w1 : w0;
    a[3] = odd ? w3 : w2;
}

// hi-only conversion (activations/features truncated to tf32)
__device__ __forceinline__ void cvtA(const float* af, uint32_t* ah) {
    #pragma unroll
    for (int i = 0; i < 4; i++) ah[i] = tf32_rna(af[i]);
}

__device__ __forceinline__ float gatherf(const float* __restrict__ tables,
                                         int lev, int comp, float qx, float qy, float s) {
    int d0 = __float2int_rd(qx * s);
    int d1 = __float2int_rd(qy * s);
    unsigned h = ((unsigned)d0 * 73856093u + (unsigned)d1 * 19349663u) & HMASK;
    return tables[(((size_t)lev << 19) + h) * 2 + comp];
}

// ---------------- prep: pack weights into per-lane MMA B-fragments ----------------
__global__ void prep_kernel(const float* __restrict__ W1, const float* __restrict__ b1,
                            const float* __restrict__ W2, const float* __restrict__ b2,
                            const float* __restrict__ W3, const float* __restrict__ b3,
                            const float* __restrict__ W4, const float* __restrict__ b4)
{
    int t = threadIdx.x;
    if (t < 736) {
        int lane = t & 31;
        const float* Wsrc; int Kdim, kt, nt, foff; bool isW4 = false;
        if (t < 384)      { int f = t >> 5;          kt = f / 4; nt = f % 4; Wsrc = W1; Kdim = 24; foff = W1F + (f * 32 + lane) * 4; }
        else if (t < 640) { int f = (t - 384) >> 5;  kt = f / 2; nt = f % 2; Wsrc = W2; Kdim = 32; foff = W2F + (f * 32 + lane) * 4; }
        else if (t < 704) { int f = (t - 640) >> 5;  kt = f;     nt = 0;     Wsrc = W3; Kdim = 16; foff = W3F + (f * 32 + lane) * 4; }
        else              { kt = 0; nt = 0; Wsrc = W4; Kdim = 8; foff = W4F + lane * 4; isW4 = true; }
        int k = kt * 8 + (lane & 3);
        int n = nt * 8 + (lane >> 2);
        bool valid = !isW4 || (n == 0);
        float v0 = valid ? Wsrc[n * Kdim + k]     : 0.0f;
        float v1 = valid ? Wsrc[n * Kdim + k + 4] : 0.0f;
        uint32_t h0, l0, h1, l1;
        split1(v0, h0, l0);
        split1(v1, h1, l1);
        g_dup[foff + 0] = __uint_as_float(h0);
        g_dup[foff + 1] = __uint_as_float(h1);
        g_dup[foff + 2] = __uint_as_float(l0);
        g_dup[foff + 3] = __uint_as_float(l1);
    } else if (t < 768) {
        g_dup[B1O + t - 736] = b1[t - 736];
    } else if (t < 784) {
        g_dup[B2O + t - 768] = b2[t - 768];
    } else if (t < 792) {
        g_dup[B3O + t - 784] = b3[t - 784];
    } else if (t < 800) {
        g_dup[B4O + t - 792] = (t == 792) ? b4[0] : 0.0f;
    }
}

// ---------------- main: warp = 16-point tile, weights in smem, A hi-only ----------------
__global__ __launch_bounds__(128, 4)
void nhgrid_mma(const float* __restrict__ x,
                const float* __restrict__ tables,
                float* __restrict__ out, int n_points, int ntiles)
{
    __shared__ __align__(16) float sWf[GTOT];

    // block-level stage of the fragment buffer (12 KB)
    {
        const float4* src = reinterpret_cast<const float4*>(g_dup);
        float4* dst = reinterpret_cast<float4*>(sWf);
        for (int k = threadIdx.x; k < GTOT / 4; k += 128) dst[k] = src[k];
    }
    __syncthreads();

    int lane = threadIdx.x & 31;
    int warpg = blockIdx.x * (blockDim.x >> 5) + (threadIdx.x >> 5);
    int nwarps = gridDim.x * (blockDim.x >> 5);
    int u = lane & 3, g = lane >> 2;
    int comp = u & 1;
    bool hb = (u >= 2);
    // per-lane spacings (full list = Python 256.0//1.6**(11-i))
    float sp[3][2];
    sp[0][0] = hb ? 2.0f  : 1.0f;   sp[0][1] = hb ? 5.0f   : 3.0f;
    sp[1][0] = hb ? 15.0f : 9.0f;   sp[1][1] = hb ? 39.0f  : 24.0f;
    sp[2][0] = hb ? 99.0f : 62.0f;  sp[2][1] = hb ? 256.0f : 159.0f;

    // biases stay in registers (10 regs)
    float2 B1r[4];
    #pragma unroll
    for (int nt = 0; nt < 4; nt++)
        B1r[nt] = *reinterpret_cast<const float2*>(sWf + B1O + nt * 8 + 2 * u);
    float2 B2r[2];
    #pragma unroll
    for (int nt = 0; nt < 2; nt++)
        B2r[nt] = *reinterpret_cast<const float2*>(sWf + B2O + nt * 8 + 2 * u);
    float2 B3r = *reinterpret_cast<const float2*>(sWf + B3O + 2 * u);
    float2 B4r = *reinterpret_cast<const float2*>(sWf + B4O + 2 * u);

    const float4* W1s = reinterpret_cast<const float4*>(sWf + W1F) + lane;
    const float4* W2s = reinterpret_cast<const float4*>(sWf + W2F) + lane;
    const float4* W3s = reinterpret_cast<const float4*>(sWf + W3F) + lane;
    const float4* W4s = reinterpret_cast<const float4*>(sWf + W4F) + lane;

    for (int tile = warpg; tile < ntiles; tile += nwarps) {
        int pbase = tile * 16;
        int p0 = pbase + g, p1 = p0 + 8;
        int m0 = min(p0, n_points - 1), m1 = min(p1, n_points - 1);
        float2 X0 = *reinterpret_cast<const float2*>(x + 2 * m0);
        float2 X1 = *reinterpret_cast<const float2*>(x + 2 * m1);
        float q00 = fmaf(X0.x, 0.5f, 0.5f), q01 = fmaf(X0.y, 0.5f, 0.5f);
        float q10 = fmaf(X1.x, 0.5f, 0.5f), q11 = fmaf(X1.y, 0.5f, 0.5f);

        // gather features into A fragments, hi-only (3 k-tiles of [16x8])
        uint32_t Ah[3][4];
        #pragma unroll
        for (int kt = 0; kt < 3; kt++) {
            int lev0 = 4 * kt + (u >> 1);
            int lev1 = lev0 + 2;
            float s0 = sp[kt][0], s1 = sp[kt][1];
            float af[4];
            af[0] = gatherf(tables, lev0, comp, q00, q01, s0);
            af[1] = gatherf(tables, lev0, comp, q10, q11, s0);
            af[2] = gatherf(tables, lev1, comp, q00, q01, s1);
            af[3] = gatherf(tables, lev1, comp, q10, q11, s1);
            cvtA(af, Ah[kt]);
        }

        // ---- layer 1: [16x24] @ [24x32], B hi/lo, weights from smem ----
        float d1t[4][4];
        #pragma unroll
        for (int nt = 0; nt < 4; nt++) {
            float* c = d1t[nt];
            c[0] = B1r[nt].x; c[1] = B1r[nt].y; c[2] = B1r[nt].x; c[3] = B1r[nt].y;
            #pragma unroll
            for (int kt = 0; kt < 3; kt++) {
                float4 wq = W1s[(kt * 4 + nt) * 32];
                uint32_t bh0 = __float_as_uint(wq.x), bh1 = __float_as_uint(wq.y);
                uint32_t bl0 = __float_as_uint(wq.z), bl1 = __float_as_uint(wq.w);
                mma8(c, Ah[kt], bh0, bh1);
                mma8(c, Ah[kt], bl0, bl1);
            }
            lrelu4(c);
        }

        // ---- layer 2: [16x32] @ [32x16], A hi-only ----
        uint32_t A2h[4][4];
        #pragma unroll
        for (int kt = 0; kt < 4; kt++) {
            float af[4];
            d2a(d1t[kt], af, lane);
            cvtA(af, A2h[kt]);
        }
        float d2t[2][4];
        #pragma unroll
        for (int nt = 0; nt < 2; nt++) {
            float* c = d2t[nt];
            c[0] = B2r[nt].x; c[1] = B2r[nt].y; c[2] = B2r[nt].x; c[3] = B2r[nt].y;
            #pragma unroll
            for (int kt = 0; kt < 4; kt++) {
                float4 wq = W2s[(kt * 2 + nt) * 32];
                uint32_t bh0 = __float_as_uint(wq.x), bh1 = __float_as_uint(wq.y);
                uint32_t bl0 = __float_as_uint(wq.z), bl1 = __float_as_uint(wq.w);
                mma8(c, A2h[kt], bh0, bh1);
                mma8(c, A2h[kt], bl0, bl1);
            }
            lrelu4(c);
        }

        // ---- layer 3: [16x16] @ [16x8], A hi-only ----
        uint32_t A3h[2][4];
        #pragma unroll
        for (int kt = 0; kt < 2; kt++) {
            float af[4];
            d2a(d2t[kt], af, lane);
            cvtA(af, A3h[kt]);
        }
        float d3t[4];
        {
            d3t[0] = B3r.x; d3t[1] = B3r.y; d3t[2] = B3r.x; d3t[3] = B3r.y;
            #pragma unroll
            for (int kt = 0; kt < 2; kt++) {
                float4 wq = W3s[kt * 32];
                uint32_t bh0 = __float_as_uint(wq.x), bh1 = __float_as_uint(wq.y);
                uint32_t bl0 = __float_as_uint(wq.z), bl1 = __float_as_uint(wq.w);
                mma8(d3t, A3h[kt], bh0, bh1);
                mma8(d3t, A3h[kt], bl0, bl1);
            }
            lrelu4(d3t);
        }

        // ---- layer 4: [16x8] @ [8x8 (1 col)], A hi-only ----
        uint32_t A4h[4];
        {
            float af[4];
            d2a(d3t, af, lane);
            cvtA(af, A4h);
        }
        float d4[4];
        {
            d4[0] = B4r.x; d4[1] = B4r.y; d4[2] = B4r.x; d4[3] = B4r.y;
            float4 wq = W4s[0];
            uint32_t bh0 = __float_as_uint(wq.x), bh1 = __float_as_uint(wq.y);
            uint32_t bl0 = __float_as_uint(wq.z), bl1 = __float_as_uint(wq.w);
            mma8(d4, A4h, bh0, bh1);
            mma8(d4, A4h, bl0, bl1);
            lrelu4(d4);   // forward's final lrelu
            lrelu4(d4);   // extra lrelu (trueRange=False)
        }

        // col 0 lives on lanes with u==0: c0 = row g, c2 = row g+8
        if (u == 0) {
            if (p0 < n_points) out[p0] = d4[0];
            if (p1 < n_points) out[p1] = d4[2];
        }
    }
}

extern "C" void kernel_launch(void* const* d_in, const int* in_sizes, int n_in,
                              void* d_out, int out_size)
{
    const float* x      = (const float*)d_in[0];
    const float* tables = (const float*)d_in[1];
    const float* W1     = (const float*)d_in[2];
    const float* b1     = (const float*)d_in[3];
    const float* W2     = (const float*)d_in[4];
    const float* b2     = (const float*)d_in[5];
    const float* W3     = (const float*)d_in[6];
    const float* b3     = (const float*)d_in[7];
    const float* W4     = (const float*)d_in[8];
    const float* b4     = (const float*)d_in[9];
    float* out = (float*)d_out;

    int n_points = in_sizes[0] / 2;
    int ntiles = (n_points + 15) / 16;

    prep_kernel<<<1, 1024>>>(W1, b1, W2, b2, W3, b3, W4, b4);

    int threads = 128;
    int blocks = 3907;           // 15628 warps; ~8 tiles per warp at 2M points
    nhgrid_mma<<<blocks, threads>>>(x, tables, out, n_points, ntiles);
}